// round 16
// baseline (speedup 1.0000x reference)
#include <cuda_runtime.h>
#include <cuda_fp16.h>
#include <cstdint>
#include <cstddef>

#define NB 4
#define NL 2048
#define NH 16
#define ND 64
#define BQ 128
#define BK 64
#define NT 128
#define NHD (NH*ND)
#define NKV (NL/BK)        // 32 kv tiles per (b,h)
#define TILW 4096          // words per fragment tile: K 2048 + V 2048 = 16KB
#define SBW 128            // words per superblock (32 lanes x 16B)
#define NSTG 3
#define QOFFW (NSTG*TILW)  // word offset of Q m=1 fragment region in smem
#define SMEM_BYTES ((NSTG*TILW + 2048) * 4)   // 48KB stages + 8KB Q = 56KB
#define PSTR 68            // prepass smem row stride (64 + 4 pad)

// precomputed fp16 fragment-format KV tiles: [bh][tile][K 8KB | V 8KB]
__device__ __align__(16) uint32_t KVfrag[(size_t)NB * NH * NKV * TILW];

__device__ __forceinline__ uint32_t smem_u32(const void* p){
    uint32_t a;
    asm("{ .reg .u64 t; cvta.to.shared.u64 t, %1; cvt.u32.u64 %0, t; }" : "=r"(a) : "l"(p));
    return a;
}
__device__ __forceinline__ float ex2f(float x){
    float r; asm("ex2.approx.ftz.f32 %0, %1;" : "=f"(r) : "f"(x)); return r;
}
__device__ __forceinline__ uint32_t h2(float a, float b){
    __half2 h = __floats2half2_rn(a, b);
    return *reinterpret_cast<uint32_t*>(&h);
}
__device__ __forceinline__ void mma16816(float* d, const uint32_t* a, uint32_t b0, uint32_t b1){
    asm volatile("mma.sync.aligned.m16n8k16.row.col.f32.f16.f16.f32 "
        "{%0,%1,%2,%3}, {%4,%5,%6,%7}, {%8,%9}, {%0,%1,%2,%3};"
        : "+f"(d[0]), "+f"(d[1]), "+f"(d[2]), "+f"(d[3])
        : "r"(a[0]), "r"(a[1]), "r"(a[2]), "r"(a[3]), "r"(b0), "r"(b1));
}

// ============ prepass: fp32 K,V -> fragment-format fp16 tiles (once) ============
__global__ __launch_bounds__(NT)
void mha_prep(const float* __restrict__ K, const float* __restrict__ V){
    __shared__ float Ks[64 * PSTR];
    __shared__ float Vs[64 * PSTR];

    const int tid = threadIdx.x;
    const int wid = tid >> 5, lid = tid & 31;
    const int g = lid >> 2, t = lid & 3;
    const int tile = blockIdx.x, bh = blockIdx.y;
    const int b = bh / NH, h = bh % NH;

    const float* Kb = K + (size_t)b * NL * NHD + (size_t)h * ND + (size_t)tile * BK * NHD;
    const float* Vb = V + (size_t)b * NL * NHD + (size_t)h * ND + (size_t)tile * BK * NHD;
    uint32_t* out = KVfrag + (size_t)(bh * NKV + tile) * TILW;

    #pragma unroll
    for (int it = 0; it < 8; it++){
        int idx = it * NT + tid;
        int r = idx >> 4, c = idx & 15;
        *(float4*)(Ks + r * PSTR + c * 4) = *(const float4*)(Kb + (size_t)r * NHD + c * 4);
        *(float4*)(Vs + r * PSTR + c * 4) = *(const float4*)(Vb + (size_t)r * NHD + c * 4);
    }
    __syncthreads();

    #pragma unroll
    for (int it = 0; it < 4; it++){
        int sb = 4 * it + wid;
        int nt = sb >> 1, kq = sb & 1;
        const float* kp_ = Ks + (8 * nt + g) * PSTR + 32 * kq + 2 * t;
        float2 k0 = *(const float2*)(kp_);
        float2 k1 = *(const float2*)(kp_ + 8);
        float2 k2 = *(const float2*)(kp_ + 16);
        float2 k3 = *(const float2*)(kp_ + 24);
        *(uint4*)(out + sb * SBW + 4 * lid) =
            make_uint4(h2(k0.x, k0.y), h2(k1.x, k1.y), h2(k2.x, k2.y), h2(k3.x, k3.y));
        int kp2 = sb >> 2, npq = sb & 3;
        const float* vp_ = Vs + (16 * kp2 + 2 * t) * PSTR + 16 * npq + g;
        float v0 = vp_[0];
        float v1 = vp_[PSTR];
        float v2 = vp_[8 * PSTR];
        float v3 = vp_[9 * PSTR];
        float v4 = vp_[8];
        float v5 = vp_[PSTR + 8];
        float v6 = vp_[8 * PSTR + 8];
        float v7 = vp_[9 * PSTR + 8];
        *(uint4*)(out + 2048 + sb * SBW + 4 * lid) =
            make_uint4(h2(v0, v1), h2(v2, v3), h2(v4, v5), h2(v6, v7));
    }
}

// ============ main kernel ============
extern __shared__ __align__(16) uint32_t stg[];   // NSTG*TILW stage words + 2048 Q words

__device__ __forceinline__ void issue_tile(const uint32_t* gsrc, uint32_t sdst, int tid){
    #pragma unroll
    for (int i = 0; i < 8; i++){
        uint32_t d = sdst + (uint32_t)(i * NT + tid) * 16;
        const uint32_t* s = gsrc + (size_t)(i * NT + tid) * 4;
        asm volatile("cp.async.cg.shared.global [%0], [%1], 16;" :: "r"(d), "l"(s) : "memory");
    }
}
#define CP_COMMIT() asm volatile("cp.async.commit_group;" ::: "memory")
#define CP_WAIT1()  asm volatile("cp.async.wait_group 1;" ::: "memory")

__global__ __launch_bounds__(NT, 3)
void mha_main(const float* __restrict__ Q, float* __restrict__ O){
    const int tid = threadIdx.x;
    const int wid = tid >> 5, lid = tid & 31;
    const int g = lid >> 2, t = lid & 3;

    const int qt = (gridDim.x - 1) - blockIdx.x;   // heavy q-tiles launch first
    const int bh = blockIdx.y;
    const int b  = bh / NH, h = bh % NH;
    const int q0 = qt * BQ;
    const int mr0 = wid * 32;                      // warp's 32 rows in the Q tile

    const float SC = 1.4426950408889634f / 8.0f;   // log2(e)/sqrt(64): base-2 softmax

    const float* Qh = Q + ((size_t)b * NL * NH + h) * ND;
    float*       Oh = O + ((size_t)b * NL * NH + h) * ND;
    const uint32_t* gkv = KVfrag + (size_t)bh * NKV * TILW;
    const uint32_t smb = smem_u32(stg);
    uint32_t* Qs = stg + QOFFW;                    // per-warp Q m=1 fragments

    // ---- Q rows -> fp16 A-fragments, pre-scaled.
    // m=0 half kept in registers; m=1 half stored to smem (per-warp private).
    uint32_t qA0[4][4];
    #pragma unroll
    for (int ks = 0; ks < 4; ks++){
        {
            const float* r0 = Qh + (size_t)(q0 + mr0 + g) * NHD + 16 * ks + 2 * t;
            const float* r1 = r0 + (size_t)8 * NHD;
            float2 f0 = *(const float2*)(r0);
            float2 f1 = *(const float2*)(r1);
            float2 f2 = *(const float2*)(r0 + 8);
            float2 f3 = *(const float2*)(r1 + 8);
            qA0[ks][0] = h2(f0.x * SC, f0.y * SC);
            qA0[ks][1] = h2(f1.x * SC, f1.y * SC);
            qA0[ks][2] = h2(f2.x * SC, f2.y * SC);
            qA0[ks][3] = h2(f3.x * SC, f3.y * SC);
        }
        {
            const float* r0 = Qh + (size_t)(q0 + mr0 + 16 + g) * NHD + 16 * ks + 2 * t;
            const float* r1 = r0 + (size_t)8 * NHD;
            float2 f0 = *(const float2*)(r0);
            float2 f1 = *(const float2*)(r1);
            float2 f2 = *(const float2*)(r0 + 8);
            float2 f3 = *(const float2*)(r1 + 8);
            *(uint4*)(Qs + ((wid * 4 + ks) * 32 + lid) * 4) =
                make_uint4(h2(f0.x * SC, f0.y * SC), h2(f1.x * SC, f1.y * SC),
                           h2(f2.x * SC, f2.y * SC), h2(f3.x * SC, f3.y * SC));
        }
    }

    float Oa[2][8][4];
    float ls[2][2];
    #pragma unroll
    for (int m = 0; m < 2; m++){
        ls[m][0] = 0.f; ls[m][1] = 0.f;
        #pragma unroll
        for (int n = 0; n < 8; n++)
            #pragma unroll
            for (int j = 0; j < 4; j++) Oa[m][n][j] = 0.f;
    }

    const int ntiles = 2 * qt + 2;                 // always >= 2
    const int rowtop = q0 + mr0 + 31;              // warp's largest q row

    // ---- prologue: async-issue tiles 0 and 1 into stages 0,1 ----
    issue_tile(gkv,        smb,            tid); CP_COMMIT();
    issue_tile(gkv + TILW, smb + TILW * 4, tid); CP_COMMIT();

    #pragma unroll 1
    for (int tt = 0; tt < ntiles; tt++){
        const int kbase = tt * BK;

        CP_WAIT1();                                // tile tt resident
        __syncthreads();

        if (tt + 2 < ntiles)
            issue_tile(gkv + (size_t)(tt + 2) * TILW,
                       smb + (uint32_t)((tt + 2) % NSTG) * TILW * 4, tid);
        CP_COMMIT();

        const uint32_t* Ks = stg + (tt % NSTG) * TILW;
        const uint32_t* Vs = Ks + 2048;
        const bool diag = (kbase >= q0);

        // ---- QK for one 16-col kv block kp into S[2][2][4] ----
        auto QKB = [&](float S[2][2][4], int kp){
            #pragma unroll
            for (int hh = 0; hh < 2; hh++)
                #pragma unroll
                for (int m = 0; m < 2; m++)
                    #pragma unroll
                    for (int j = 0; j < 4; j++) S[hh][m][j] = 0.f;
            #pragma unroll
            for (int kq = 0; kq < 2; kq++){
                uint4 q1a = *(const uint4*)(Qs + ((wid * 4 + 2 * kq)     * 32 + lid) * 4);
                uint4 q1b = *(const uint4*)(Qs + ((wid * 4 + 2 * kq + 1) * 32 + lid) * 4);
                #pragma unroll
                for (int hh = 0; hh < 2; hh++){
                    uint4 kb = *(const uint4*)(Ks + (((2 * kp + hh) * 2 + kq)) * SBW + 4 * lid);
                    mma16816(S[hh][0], qA0[2 * kq],     kb.x, kb.y);
                    mma16816(S[hh][0], qA0[2 * kq + 1], kb.z, kb.w);
                    mma16816(S[hh][1], (const uint32_t*)&q1a, kb.x, kb.y);
                    mma16816(S[hh][1], (const uint32_t*)&q1b, kb.z, kb.w);
                }
            }
        };
        // ---- softmax + PV for block kp from S ----
        auto SMPV = [&](float S[2][2][4], int kp){
            uint32_t pA[2][4];
            #pragma unroll
            for (int m = 0; m < 2; m++){
                #pragma unroll
                for (int hh = 0; hh < 2; hh++){
                    float p0 = ex2f(S[hh][m][0]);
                    float p1 = ex2f(S[hh][m][1]);
                    float p2 = ex2f(S[hh][m][2]);
                    float p3 = ex2f(S[hh][m][3]);
                    if (diag){
                        int rg = q0 + mr0 + 16 * m + g;
                        int cg = kbase + 16 * kp + 8 * hh + 2 * t;
                        if (cg     > rg)     p0 = 0.f;
                        if (cg + 1 > rg)     p1 = 0.f;
                        if (cg     > rg + 8) p2 = 0.f;
                        if (cg + 1 > rg + 8) p3 = 0.f;
                    }
                    ls[m][0] += p0 + p1;
                    ls[m][1] += p2 + p3;
                    pA[m][2*hh]     = h2(p0, p1);
                    pA[m][2*hh + 1] = h2(p2, p3);
                }
            }
            #pragma unroll
            for (int npq = 0; npq < 4; npq++){
                uint4 vb = *(const uint4*)(Vs + (kp * 4 + npq) * SBW + 4 * lid);
                mma16816(Oa[0][2*npq],   pA[0], vb.x, vb.y);
                mma16816(Oa[0][2*npq+1], pA[0], vb.z, vb.w);
                mma16816(Oa[1][2*npq],   pA[1], vb.x, vb.y);
                mma16816(Oa[1][2*npq+1], pA[1], vb.z, vb.w);
            }
        };

        float Sa[2][2][4], Sb[2][2][4];
        int kplim = 4;
        if (diag){
            int d = (rowtop - kbase) >> 4;
            kplim = d < 0 ? 0 : (d > 2 ? 4 : d + 1);
        }
        if (kplim == 4){
            // full pipelined schedule: QK(kp+1) overlaps softmax+PV(kp)
            QKB(Sa, 0);
            QKB(Sb, 1);
            SMPV(Sa, 0);
            QKB(Sa, 2);
            SMPV(Sb, 1);
            QKB(Sb, 3);
            SMPV(Sa, 2);
            SMPV(Sb, 3);
        } else if (kplim > 0){
            QKB(Sa, 0);
            if (kplim > 1) QKB(Sb, 1);
            SMPV(Sa, 0);
            if (kplim > 2){
                QKB(Sa, 2);
                SMPV(Sb, 1);
                SMPV(Sa, 2);
            } else if (kplim > 1){
                SMPV(Sb, 1);
            }
        }
        __syncthreads();    // stage may be overwritten next iteration
    }

    // ---- epilogue: quad-reduce row sums, normalize, store ----
    #pragma unroll
    for (int m = 0; m < 2; m++){
        float s0 = ls[m][0], s1 = ls[m][1];
        s0 += __shfl_xor_sync(0xffffffffu, s0, 1);
        s0 += __shfl_xor_sync(0xffffffffu, s0, 2);
        s1 += __shfl_xor_sync(0xffffffffu, s1, 1);
        s1 += __shfl_xor_sync(0xffffffffu, s1, 2);
        float i0 = 1.f / s0, i1 = 1.f / s1;
        int rg = q0 + mr0 + 16 * m + g;
        float* o0 = Oh + (size_t)rg * NHD + 2 * t;
        float* o1 = o0 + 8 * (size_t)NHD;
        #pragma unroll
        for (int n = 0; n < 8; n++){
            *(float2*)(o0 + 8 * n) = make_float2(Oa[m][n][0] * i0, Oa[m][n][1] * i0);
            *(float2*)(o1 + 8 * n) = make_float2(Oa[m][n][2] * i1, Oa[m][n][3] * i1);
        }
    }
}

extern "C" void kernel_launch(void* const* d_in, const int* in_sizes, int n_in,
                              void* d_out, int out_size)
{
    const float* q = (const float*)d_in[0];
    const float* k = (const float*)d_in[1];
    const float* v = (const float*)d_in[2];
    float* o = (float*)d_out;

    dim3 pgrid(NKV, NB * NH);                // (32, 64)
    mha_prep<<<pgrid, NT>>>(k, v);

    static bool attr_set = false;
    if (!attr_set){
        cudaFuncSetAttribute(mha_main, cudaFuncAttributeMaxDynamicSharedMemorySize,
                             SMEM_BYTES);
        attr_set = true;
    }
    dim3 grid(NL / BQ, NB * NH);             // (16, 64)
    mha_main<<<grid, NT, SMEM_BYTES>>>(q, o);
}

// round 17
// speedup vs baseline: 1.3469x; 1.3469x over previous
#include <cuda_runtime.h>
#include <cuda_fp16.h>
#include <cstdint>
#include <cstddef>

#define NB 4
#define NL 2048
#define NH 16
#define ND 64
#define BQ 128
#define BK 64
#define NT 128
#define NHD (NH*ND)
#define NKV (NL/BK)        // 32 kv tiles per (b,h)
#define NBH (NB*NH)        // 64
#define TILW 4096          // words per fragment tile: K 2048 + V 2048 = 16KB
#define SBW 128            // words per superblock (32 lanes x 16B)
#define NSTG 3
#define PSTR 68            // prepass smem row stride (64 + 4 pad)
#define NPREP (NBH*NKV)    // 2048 prepass blocks
#define NMAIN ((NL/BQ)*NBH) // 1024 main blocks

// precomputed fp16 fragment-format KV tiles: [bh][tile][K 8KB | V 8KB]
__device__ __align__(16) uint32_t KVfrag[(size_t)NBH * NKV * TILW];
__device__ uint32_t tileflag[NPREP];

__device__ __forceinline__ uint32_t smem_u32(const void* p){
    uint32_t a;
    asm("{ .reg .u64 t; cvta.to.shared.u64 t, %1; cvt.u32.u64 %0, t; }" : "=r"(a) : "l"(p));
    return a;
}
__device__ __forceinline__ float ex2f(float x){
    float r; asm("ex2.approx.ftz.f32 %0, %1;" : "=f"(r) : "f"(x)); return r;
}
__device__ __forceinline__ uint32_t h2(float a, float b){
    __half2 h = __floats2half2_rn(a, b);
    return *reinterpret_cast<uint32_t*>(&h);
}
__device__ __forceinline__ void mma16816(float* d, const uint32_t* a, uint32_t b0, uint32_t b1){
    asm volatile("mma.sync.aligned.m16n8k16.row.col.f32.f16.f16.f32 "
        "{%0,%1,%2,%3}, {%4,%5,%6,%7}, {%8,%9}, {%0,%1,%2,%3};"
        : "+f"(d[0]), "+f"(d[1]), "+f"(d[2]), "+f"(d[3])
        : "r"(a[0]), "r"(a[1]), "r"(a[2]), "r"(a[3]), "r"(b0), "r"(b1));
}
__device__ __forceinline__ void flag_set(uint32_t* f){
    asm volatile("st.release.gpu.b32 [%0], %1;" :: "l"(f), "r"(1u) : "memory");
}
__device__ __forceinline__ void flag_wait(const uint32_t* f){
    uint32_t v;
    while (true){
        asm volatile("ld.acquire.gpu.b32 %0, [%1];" : "=r"(v) : "l"(f));
        if (v) break;
        __nanosleep(64);
    }
}

__global__ void flags_zero(){
    int i = blockIdx.x * blockDim.x + threadIdx.x;
    if (i < NPREP) tileflag[i] = 0;
}

extern __shared__ __align__(16) uint32_t dsm[];   // 48KB: main stages / prepass staging

#define CP_COMMIT() asm volatile("cp.async.commit_group;" ::: "memory")
#define CP_WAIT1()  asm volatile("cp.async.wait_group 1;" ::: "memory")

__device__ __forceinline__ void issue_tile(const uint32_t* gsrc, uint32_t sdst, int tid){
    #pragma unroll
    for (int i = 0; i < 8; i++){
        uint32_t d = sdst + (uint32_t)(i * NT + tid) * 16;
        const uint32_t* s = gsrc + (size_t)(i * NT + tid) * 4;
        asm volatile("cp.async.cg.shared.global [%0], [%1], 16;" :: "r"(d), "l"(s) : "memory");
    }
}

__global__ __launch_bounds__(NT, 3)
void mha_fused(const float* __restrict__ Q, const float* __restrict__ K,
               const float* __restrict__ V, float* __restrict__ O)
{
    const int tid = threadIdx.x;
    const int wid = tid >> 5, lid = tid & 31;
    const int g = lid >> 2, t = lid & 3;

    if (blockIdx.x < NPREP){
        // ================= prepass role: convert one KV tile =================
        const int pb = blockIdx.x;
        const int tile = pb >> 6;          // tile-major: all bh's tile 0 first
        const int bh = pb & 63;
        const int b = bh / NH, h = bh % NH;

        float* Ks = (float*)dsm;                   // 64*PSTR floats
        float* Vs = Ks + 64 * PSTR;

        const float* Kb = K + (size_t)b * NL * NHD + (size_t)h * ND + (size_t)tile * BK * NHD;
        const float* Vb = V + (size_t)b * NL * NHD + (size_t)h * ND + (size_t)tile * BK * NHD;
        uint32_t* out = KVfrag + (size_t)(bh * NKV + tile) * TILW;

        #pragma unroll
        for (int it = 0; it < 8; it++){
            int idx = it * NT + tid;
            int r = idx >> 4, c = idx & 15;
            *(float4*)(Ks + r * PSTR + c * 4) = *(const float4*)(Kb + (size_t)r * NHD + c * 4);
            *(float4*)(Vs + r * PSTR + c * 4) = *(const float4*)(Vb + (size_t)r * NHD + c * 4);
        }
        __syncthreads();

        #pragma unroll
        for (int it = 0; it < 4; it++){
            int sb = 4 * it + wid;
            int nt = sb >> 1, kq = sb & 1;
            const float* kp_ = Ks + (8 * nt + g) * PSTR + 32 * kq + 2 * t;
            float2 k0 = *(const float2*)(kp_);
            float2 k1 = *(const float2*)(kp_ + 8);
            float2 k2 = *(const float2*)(kp_ + 16);
            float2 k3 = *(const float2*)(kp_ + 24);
            *(uint4*)(out + sb * SBW + 4 * lid) =
                make_uint4(h2(k0.x, k0.y), h2(k1.x, k1.y), h2(k2.x, k2.y), h2(k3.x, k3.y));
            int kp2 = sb >> 2, npq = sb & 3;
            const float* vp_ = Vs + (16 * kp2 + 2 * t) * PSTR + 16 * npq + g;
            float v0 = vp_[0];
            float v1 = vp_[PSTR];
            float v2 = vp_[8 * PSTR];
            float v3 = vp_[9 * PSTR];
            float v4 = vp_[8];
            float v5 = vp_[PSTR + 8];
            float v6 = vp_[8 * PSTR + 8];
            float v7 = vp_[9 * PSTR + 8];
            *(uint4*)(out + 2048 + sb * SBW + 4 * lid) =
                make_uint4(h2(v0, v1), h2(v2, v3), h2(v4, v5), h2(v6, v7));
        }
        __syncthreads();                   // all 128 threads' STGs done (cta order)
        if (tid == 0) flag_set(&tileflag[bh * NKV + tile]);   // release at gpu scope
        return;
    }

    // ================= main role: R12 mainloop + flag-gated streaming =================
    const int mb = blockIdx.x - NPREP;
    const int bh = mb & 63;
    const int qt = (NL / BQ - 1) - (mb >> 6);      // heavy q-tiles first
    const int b  = bh / NH, h = bh % NH;
    const int q0 = qt * BQ;
    const int mr0 = wid * 32;

    const float SC = 1.4426950408889634f / 8.0f;   // log2(e)/sqrt(64): base-2 softmax

    const float* Qh = Q + ((size_t)b * NL * NH + h) * ND;
    float*       Oh = O + ((size_t)b * NL * NH + h) * ND;
    const uint32_t* gkv = KVfrag + (size_t)bh * NKV * TILW;
    const uint32_t* flg = tileflag + bh * NKV;
    const uint32_t smb = smem_u32(dsm);

    // ---- Q rows -> fp16 A-fragments (2 m-tiles x 4 k16-steps), pre-scaled ----
    uint32_t qA[2][4][4];
    #pragma unroll
    for (int m = 0; m < 2; m++)
        #pragma unroll
        for (int ks = 0; ks < 4; ks++){
            const float* r0 = Qh + (size_t)(q0 + mr0 + 16 * m + g) * NHD + 16 * ks + 2 * t;
            const float* r1 = r0 + (size_t)8 * NHD;
            float2 f0 = *(const float2*)(r0);
            float2 f1 = *(const float2*)(r1);
            float2 f2 = *(const float2*)(r0 + 8);
            float2 f3 = *(const float2*)(r1 + 8);
            qA[m][ks][0] = h2(f0.x * SC, f0.y * SC);
            qA[m][ks][1] = h2(f1.x * SC, f1.y * SC);
            qA[m][ks][2] = h2(f2.x * SC, f2.y * SC);
            qA[m][ks][3] = h2(f3.x * SC, f3.y * SC);
        }

    float Oa[2][8][4];
    float ls[2][2];
    #pragma unroll
    for (int m = 0; m < 2; m++){
        ls[m][0] = 0.f; ls[m][1] = 0.f;
        #pragma unroll
        for (int n = 0; n < 8; n++)
            #pragma unroll
            for (int j = 0; j < 4; j++) Oa[m][n][j] = 0.f;
    }

    const int ntiles = 2 * qt + 2;                 // always >= 2
    const int rowtop = q0 + mr0 + 31;              // warp's largest q row

    // ---- prologue: wait + async-issue tiles 0 and 1 ----
    flag_wait(&flg[0]);
    issue_tile(gkv,        smb,            tid); CP_COMMIT();
    flag_wait(&flg[1]);
    issue_tile(gkv + TILW, smb + TILW * 4, tid); CP_COMMIT();

    #pragma unroll 1
    for (int tt = 0; tt < ntiles; tt++){
        const int kbase = tt * BK;

        CP_WAIT1();                                // tile tt resident
        __syncthreads();

        if (tt + 2 < ntiles){
            flag_wait(&flg[tt + 2]);
            issue_tile(gkv + (size_t)(tt + 2) * TILW,
                       smb + (uint32_t)((tt + 2) % NSTG) * TILW * 4, tid);
        }
        CP_COMMIT();

        const uint32_t* Ks = dsm + (tt % NSTG) * TILW;
        const uint32_t* Vs = Ks + 2048;
        const bool diag = (kbase >= q0);

        #pragma unroll
        for (int kp = 0; kp < 4; kp++){                       // 16 kv cols per step
            if (diag && (kbase + 16 * kp > rowtop)) continue; // warp-uniform skip

            // ---- QK^T for kv cols [16kp, 16kp+16) ----
            float S4[2][2][4];                                 // [hh][m][4]
            #pragma unroll
            for (int hh = 0; hh < 2; hh++)
                #pragma unroll
                for (int m = 0; m < 2; m++)
                    #pragma unroll
                    for (int j = 0; j < 4; j++) S4[hh][m][j] = 0.f;
            #pragma unroll
            for (int hh = 0; hh < 2; hh++){
                int nt = 2 * kp + hh;
                #pragma unroll
                for (int kq = 0; kq < 2; kq++){
                    uint4 kb = *(const uint4*)(Ks + (nt * 2 + kq) * SBW + 4 * lid);
                    mma16816(S4[hh][0], qA[0][2*kq],   kb.x, kb.y);
                    mma16816(S4[hh][0], qA[0][2*kq+1], kb.z, kb.w);
                    mma16816(S4[hh][1], qA[1][2*kq],   kb.x, kb.y);
                    mma16816(S4[hh][1], qA[1][2*kq+1], kb.z, kb.w);
                }
            }

            // ---- softmax: p = exp2(s), causal mask, in-lane pack to A-frags ----
            uint32_t pA[2][4];
            #pragma unroll
            for (int m = 0; m < 2; m++){
                #pragma unroll
                for (int hh = 0; hh < 2; hh++){
                    float p0 = ex2f(S4[hh][m][0]);
                    float p1 = ex2f(S4[hh][m][1]);
                    float p2 = ex2f(S4[hh][m][2]);
                    float p3 = ex2f(S4[hh][m][3]);
                    if (diag){
                        int rg = q0 + mr0 + 16 * m + g;
                        int cg = kbase + 16 * kp + 8 * hh + 2 * t;
                        if (cg     > rg)     p0 = 0.f;
                        if (cg + 1 > rg)     p1 = 0.f;
                        if (cg     > rg + 8) p2 = 0.f;
                        if (cg + 1 > rg + 8) p3 = 0.f;
                    }
                    ls[m][0] += p0 + p1;
                    ls[m][1] += p2 + p3;
                    pA[m][2*hh]     = h2(p0, p1);   // rows g,   k = 8hh+2t, +1
                    pA[m][2*hh + 1] = h2(p2, p3);   // rows g+8
                }
            }

            // ---- PV accumulate (k16-step = kp) ----
            #pragma unroll
            for (int npq = 0; npq < 4; npq++){
                uint4 vb = *(const uint4*)(Vs + (kp * 4 + npq) * SBW + 4 * lid);
                mma16816(Oa[0][2*npq],   pA[0], vb.x, vb.y);
                mma16816(Oa[0][2*npq+1], pA[0], vb.z, vb.w);
                mma16816(Oa[1][2*npq],   pA[1], vb.x, vb.y);
                mma16816(Oa[1][2*npq+1], pA[1], vb.z, vb.w);
            }
        }
        __syncthreads();    // stage may be overwritten next iteration
    }

    // ---- epilogue: quad-reduce row sums, normalize, store ----
    #pragma unroll
    for (int m = 0; m < 2; m++){
        float s0 = ls[m][0], s1 = ls[m][1];
        s0 += __shfl_xor_sync(0xffffffffu, s0, 1);
        s0 += __shfl_xor_sync(0xffffffffu, s0, 2);
        s1 += __shfl_xor_sync(0xffffffffu, s1, 1);
        s1 += __shfl_xor_sync(0xffffffffu, s1, 2);
        float i0 = 1.f / s0, i1 = 1.f / s1;
        int rg = q0 + mr0 + 16 * m + g;
        float* o0 = Oh + (size_t)rg * NHD + 2 * t;
        float* o1 = o0 + 8 * (size_t)NHD;
        #pragma unroll
        for (int n = 0; n < 8; n++){
            *(float2*)(o0 + 8 * n) = make_float2(Oa[m][n][0] * i0, Oa[m][n][1] * i0);
            *(float2*)(o1 + 8 * n) = make_float2(Oa[m][n][2] * i1, Oa[m][n][3] * i1);
        }
    }
}

extern "C" void kernel_launch(void* const* d_in, const int* in_sizes, int n_in,
                              void* d_out, int out_size)
{
    const float* q = (const float*)d_in[0];
    const float* k = (const float*)d_in[1];
    const float* v = (const float*)d_in[2];
    float* o = (float*)d_out;

    flags_zero<<<(NPREP + 255) / 256, 256>>>();

    static bool attr_set = false;
    if (!attr_set){
        cudaFuncSetAttribute(mha_fused, cudaFuncAttributeMaxDynamicSharedMemorySize,
                             NSTG * TILW * 4);
        attr_set = true;
    }
    mha_fused<<<NPREP + NMAIN, NT, NSTG * TILW * 4>>>(q, k, v, o);
}